// round 3
// baseline (speedup 1.0000x reference)
#include <cuda_runtime.h>
#include <math.h>

// Problem constants (fixed by the dataset)
#define BB   256   // batch
#define TT   512   // time steps
#define HH   512   // hidden
#define II   256   // input dim
#define N4H  2048  // 4*H gate columns

// Tiling
#define BT   32    // batch tile per CTA
#define HT   32    // h tile per CTA
#define KC   32    // K chunk
#define NCTA 128   // (256/32) * (512/32) = 8 * 16
#define NTHR 256   // 8 warps

// Inter-step double-buffered hidden state + grid barrier state
__device__ float g_hbuf[2][BB * HH];
__device__ unsigned int g_arr;
__device__ unsigned int g_gen;

// ---- packed f32x2 helpers (Blackwell) ----
__device__ __forceinline__ unsigned long long pk2(float a, float b) {
    unsigned long long r;
    asm("mov.b64 %0, {%1,%2};" : "=l"(r) : "f"(a), "f"(b));
    return r;
}
__device__ __forceinline__ void upk2(unsigned long long v, float &a, float &b) {
    asm("mov.b64 {%0,%1}, %2;" : "=f"(a), "=f"(b) : "l"(v));
}
__device__ __forceinline__ void fma2(unsigned long long &d, unsigned long long a,
                                     unsigned long long b) {
    asm("fma.rn.f32x2 %0, %1, %2, %0;" : "+l"(d) : "l"(a), "l"(b));
}
__device__ __forceinline__ float sigmf_(float x) { return 1.0f / (1.0f + expf(-x)); }

// ---- software grid barrier (sense via generation counter) ----
__device__ __forceinline__ void gridbar() {
    __syncthreads();
    if (threadIdx.x == 0) {
        unsigned int gen = *((volatile unsigned int *)&g_gen);
        __threadfence();
        if (atomicAdd(&g_arr, 1u) == (unsigned int)(NCTA - 1)) {
            g_arr = 0u;
            __threadfence();
            *((volatile unsigned int *)&g_gen) = gen + 1u;
        } else {
            while (*((volatile unsigned int *)&g_gen) == gen) { __nanosleep(64); }
        }
    }
    __syncthreads();
    __threadfence();  // acquire: make other CTAs' h writes visible
}

struct SMem {
    float  h[KC][BT + 1];   // +1 pad: conflict-free strided store / row read
    float4 u4[KC][32];      // [k][g*8 + hl4] : col layout g*32 + hl (floats)
};

// acc[2g+jp] accumulates gate g for h-pair (hl = w*4+2jp, +1), b = b0+lane.
template <bool CG>
__device__ __forceinline__ void gemm_acc(
    unsigned long long acc[8],
    const float *__restrict__ src, int lds,      // src[b*lds + k]
    const float *__restrict__ Wm,                // Wm[k*2048 + n]
    int K, int b0, int h0i, int tid, int lane, int w,
    bool xc, float tau, SMem *sm)
{
    const int bl = tid >> 3;          // 0..31 batch row (local)
    const int kb = (tid & 7) << 2;    // 0,4,...,28 k offset
    const float *hp = src + (size_t)(b0 + bl) * lds + kb;

    float4 hreg;
    float4 ureg[4];

    // preload chunk 0
    hreg = CG ? __ldcg((const float4 *)hp) : *(const float4 *)hp;
    if (xc && kb == 0) {  // on-the-fly xcorr on h[:,0:2] (this float4 holds k=0..3)
        float a = hreg.x, b = hreg.y;
        hreg.x = a + tau * (1.5f * a + b * (1.0f / 1.5f));
        hreg.y = b + tau * (-1.5f * a);
    }
#pragma unroll
    for (int r = 0; r < 4; ++r) {
        int idx = tid + NTHR * r;
        int kc = idx >> 5, c4 = idx & 31;
        ureg[r] = *(const float4 *)(Wm + (size_t)kc * N4H + ((c4 >> 3) << 9) + h0i +
                                    ((c4 & 7) << 2));
    }

    for (int k0 = 0; k0 < K; k0 += KC) {
        __syncthreads();
        sm->h[kb + 0][bl] = hreg.x;
        sm->h[kb + 1][bl] = hreg.y;
        sm->h[kb + 2][bl] = hreg.z;
        sm->h[kb + 3][bl] = hreg.w;
#pragma unroll
        for (int r = 0; r < 4; ++r) {
            int idx = tid + NTHR * r;
            sm->u4[idx >> 5][idx & 31] = ureg[r];
        }
        __syncthreads();

        const int kn = k0 + KC;
        if (kn < K) {  // prefetch next chunk while computing
            const float *hp2 = hp + kn;
            hreg = CG ? __ldcg((const float4 *)hp2) : *(const float4 *)hp2;
#pragma unroll
            for (int r = 0; r < 4; ++r) {
                int idx = tid + NTHR * r;
                int kc = idx >> 5, c4 = idx & 31;
                ureg[r] = *(const float4 *)(Wm + (size_t)(kn + kc) * N4H +
                                            ((c4 >> 3) << 9) + h0i + ((c4 & 7) << 2));
            }
        }

        const float *uf = (const float *)sm->u4;
        const float *hf = &sm->h[0][0];
#pragma unroll 8
        for (int k = 0; k < KC; ++k) {
            float hv = hf[k * (BT + 1) + lane];
            unsigned long long hh = pk2(hv, hv);
            const unsigned long long *row =
                (const unsigned long long *)(uf + k * 128 + (w << 2));
            fma2(acc[0], row[0],  hh);   // gate 0, h pair 0
            fma2(acc[1], row[1],  hh);   // gate 0, h pair 1
            fma2(acc[2], row[16], hh);   // gate 1
            fma2(acc[3], row[17], hh);
            fma2(acc[4], row[32], hh);   // gate 2
            fma2(acc[5], row[33], hh);
            fma2(acc[6], row[48], hh);   // gate 3
            fma2(acc[7], row[49], hh);
        }
    }
}

__global__ void __launch_bounds__(NTHR, 1) lstm_persist(
    const float *__restrict__ rnn, const int *__restrict__ bsz,
    const float *__restrict__ h0in, const float *__restrict__ c0in,
    const float *__restrict__ taup, const float *__restrict__ Ww,
    const float *__restrict__ Wb, const float *__restrict__ Uw,
    float *__restrict__ out)
{
    __shared__ SMem sm;
    const int tid  = threadIdx.x;
    const int lane = tid & 31;
    const int w    = tid >> 5;
    const int cta  = blockIdx.x;
    const int b0   = (cta & 7) * BT;    // 8 batch tiles
    const int h0i  = (cta >> 3) * HT;   // 16 h tiles
    const float tau = *taup;
    const int hbase = h0i + (w << 2);   // this thread's 4 h indices
    const int b = b0 + lane;            // this thread's batch row

    // ---- pre = x0 @ W_w + W_b (kept in registers, time-invariant) ----
    unsigned long long pre[8];
#pragma unroll
    for (int i = 0; i < 8; ++i) pre[i] = 0ull;
    gemm_acc<false>(pre, rnn, II, Ww, II, b0, h0i, tid, lane, w, false, 0.0f, &sm);
#pragma unroll
    for (int g = 0; g < 4; ++g) {
#pragma unroll
        for (int jp = 0; jp < 2; ++jp) {
            float a, c;
            upk2(pre[g * 2 + jp], a, c);
            int col = (g << 9) + hbase + (jp << 1);
            pre[g * 2 + jp] = pk2(a + Wb[col], c + Wb[col + 1]);
        }
    }

    // ---- c lives in registers for all 512 steps ----
    float creg[4], hlast[4];
#pragma unroll
    for (int j = 0; j < 4; ++j) creg[j] = c0in[(size_t)b * HH + hbase + j];
#pragma unroll
    for (int j = 0; j < 4; ++j) hlast[j] = 0.0f;

    for (int t = 0; t < TT; ++t) {
        const float *hsrc = (t == 0) ? h0in : g_hbuf[(t + 1) & 1];
        float *hdst = g_hbuf[t & 1];

        unsigned long long acc[8];
#pragma unroll
        for (int i = 0; i < 8; ++i) acc[i] = pre[i];
        gemm_acc<true>(acc, hsrc, HH, Uw, HH, b0, h0i, tid, lane, w, (t > 0), tau, &sm);

        const int bs = bsz[t];
        const bool act = (b < bs);

        float gv[4][4];  // [gate][j]
#pragma unroll
        for (int g = 0; g < 4; ++g) {
            upk2(acc[g * 2 + 0], gv[g][0], gv[g][1]);
            upk2(acc[g * 2 + 1], gv[g][2], gv[g][3]);
        }

        const float *hrow = hsrc + (size_t)b * HH;
        float *orow = out + (size_t)t * BB * HH + (size_t)b * HH;
        float *drow = hdst + (size_t)b * HH;
#pragma unroll
        for (int j = 0; j < 4; ++j) {
            float cn = sigmf_(gv[1][j]) * creg[j] + sigmf_(gv[0][j]) * tanhf(gv[2][j]);
            float hn = sigmf_(gv[3][j]) * tanhf(cn);
            float hw, ow;
            if (act) {
                creg[j] = cn;
                hw = hn;
                ow = hn;
            } else {
                int hj = hbase + j;
                float old = __ldcg(hrow + hj);
                if (t > 0 && hj < 2) {  // inactive rows still drift on dims 0,1
                    float a0 = __ldcg(hrow + 0), a1 = __ldcg(hrow + 1);
                    old = (hj == 0) ? (a0 + tau * (1.5f * a0 + a1 * (1.0f / 1.5f)))
                                    : (a1 + tau * (-1.5f * a0));
                }
                hw = old;
                ow = 0.0f;
            }
            hlast[j] = hw;
            __stcg(drow + hbase + j, hw);
            orow[hbase + j] = ow;
        }
        gridbar();
    }

    // ---- final h, c appended after outputs ----
    const size_t ofs = (size_t)TT * BB * HH;
#pragma unroll
    for (int j = 0; j < 4; ++j) {
        out[ofs + (size_t)b * HH + hbase + j] = hlast[j];
        out[ofs + (size_t)BB * HH + (size_t)b * HH + hbase + j] = creg[j];
    }
}

extern "C" void kernel_launch(void *const *d_in, const int *in_sizes, int n_in,
                              void *d_out, int out_size)
{
    const float *rnn  = (const float *)d_in[0];  // (B*T, I) fp32 — only first B rows used
    const int   *bsz  = (const int *)d_in[1];    // (T,) int32
    const float *h0   = (const float *)d_in[2];  // (1,B,H)
    const float *c0   = (const float *)d_in[3];  // (1,B,H)
    const float *tau  = (const float *)d_in[4];  // scalar
    const float *Ww   = (const float *)d_in[5];  // (I,4H)
    const float *Wb   = (const float *)d_in[6];  // (4H,)
    const float *Uw   = (const float *)d_in[7];  // (H,4H)
    float *out = (float *)d_out;                 // T*B*H outputs, then h, then c

    lstm_persist<<<NCTA, NTHR>>>(rnn, bsz, h0, c0, tau, Ww, Wb, Uw, out);
}

// round 5
// speedup vs baseline: 3.2784x; 3.2784x over previous
#include <cuda_runtime.h>
#include <cuda_bf16.h>
#include <stdint.h>

#define BB 256
#define TT 512
#define HH 512
#define II 256
#define BH 131072
#define NCTA 128
#define NTHR 256

// SMEM layout (dynamic): A dbl-buf 2x(8K hi + 8K lo) = 32K, then U/W hi 64K, lo 64K
#define SO_UH 32768
#define SO_UL 98304
#define SMEM_TOT 163840

// ---------------- device globals (16B aligned for cp.async/uint4) ----------------
__device__ __align__(16) __nv_bfloat16 g_Ut_hi[2048 * 512];
__device__ __align__(16) __nv_bfloat16 g_Ut_lo[2048 * 512];
__device__ __align__(16) __nv_bfloat16 g_Wt_hi[2048 * 256];
__device__ __align__(16) __nv_bfloat16 g_Wt_lo[2048 * 256];
__device__ __align__(16) __nv_bfloat16 g_x0_hi[256 * 256];
__device__ __align__(16) __nv_bfloat16 g_x0_lo[256 * 256];
__device__ __align__(16) __nv_bfloat16 g_ahi[2][BH];
__device__ __align__(16) __nv_bfloat16 g_alo[2][BH];
__device__ unsigned int g_arr;
__device__ unsigned int g_gen;

// ---------------- helpers ----------------
__device__ __forceinline__ uint32_t smem_u32(const void *p) {
    uint32_t a;
    asm("{ .reg .u64 t; cvta.to.shared.u64 t, %1; cvt.u32.u64 %0, t; }"
        : "=r"(a) : "l"(p));
    return a;
}
__device__ __forceinline__ void cpa16(uint32_t dst, const void *src) {
    asm volatile("cp.async.cg.shared.global [%0], [%1], 16;"
                 :: "r"(dst), "l"(__cvta_generic_to_global(src)) : "memory");
}
#define CP_COMMIT asm volatile("cp.async.commit_group;" ::: "memory")
#define CP_WAIT0  asm volatile("cp.async.wait_group 0;" ::: "memory")

__device__ __forceinline__ void ldsm4(uint32_t addr, uint32_t r[4]) {
    asm volatile("ldmatrix.sync.aligned.m8n8.x4.shared.b16 {%0,%1,%2,%3}, [%4];"
                 : "=r"(r[0]), "=r"(r[1]), "=r"(r[2]), "=r"(r[3]) : "r"(addr));
}
__device__ __forceinline__ void mmabf(float c[4], const uint32_t a[4],
                                      uint32_t b0, uint32_t b1) {
    asm volatile(
        "mma.sync.aligned.m16n8k16.row.col.f32.bf16.bf16.f32 "
        "{%0,%1,%2,%3}, {%4,%5,%6,%7}, {%8,%9}, {%0,%1,%2,%3};"
        : "+f"(c[0]), "+f"(c[1]), "+f"(c[2]), "+f"(c[3])
        : "r"(a[0]), "r"(a[1]), "r"(a[2]), "r"(a[3]), "r"(b0), "r"(b1));
}
__device__ __forceinline__ float sigf(float x) {
    return __fdividef(1.0f, 1.0f + __expf(-x));
}
__device__ __forceinline__ float tanhfast(float x) {
    return 1.0f - __fdividef(2.0f, __expf(2.0f * x) + 1.0f);
}

__device__ __forceinline__ void gridbar() {
    __syncthreads();
    if (threadIdx.x == 0) {
        unsigned int gen = *((volatile unsigned int *)&g_gen);
        __threadfence();
        if (atomicAdd(&g_arr, 1u) == (unsigned int)(NCTA - 1)) {
            g_arr = 0u;
            __threadfence();
            *((volatile unsigned int *)&g_gen) = gen + 1u;
        } else {
            while (*((volatile unsigned int *)&g_gen) == gen) { __nanosleep(32); }
        }
    }
    __syncthreads();
    __threadfence();
}

// ---------------- prep: permute cols (gate-interleave) + bf16 split ----------------
__global__ void prep_kernel(const float *__restrict__ rnn,
                            const float *__restrict__ h0,
                            const float *__restrict__ Ww,
                            const float *__restrict__ Uw)
{
    const long TU = 512L * 2048, TW = 256L * 2048, TX = 256L * 256, TH = 256L * 512;
    const long TOT = TU + TW + TX + TH;
    for (long i = (long)blockIdx.x * blockDim.x + threadIdx.x; i < TOT;
         i += (long)gridDim.x * blockDim.x) {
        if (i < TU) {
            long k = i >> 11;
            int n = (int)(i & 2047);
            int p = ((n & 511) << 2) | (n >> 9);   // h*4 + gate
            float v = Uw[i];
            __nv_bfloat16 hi = __float2bfloat16_rn(v);
            g_Ut_hi[(long)p * 512 + k] = hi;
            g_Ut_lo[(long)p * 512 + k] = __float2bfloat16_rn(v - __bfloat162float(hi));
        } else if (i < TU + TW) {
            long j = i - TU;
            long k = j >> 11;
            int n = (int)(j & 2047);
            int p = ((n & 511) << 2) | (n >> 9);
            float v = Ww[j];
            __nv_bfloat16 hi = __float2bfloat16_rn(v);
            g_Wt_hi[(long)p * 256 + k] = hi;
            g_Wt_lo[(long)p * 256 + k] = __float2bfloat16_rn(v - __bfloat162float(hi));
        } else if (i < TU + TW + TX) {
            long j = i - TU - TW;
            float v = rnn[j];
            __nv_bfloat16 hi = __float2bfloat16_rn(v);
            g_x0_hi[j] = hi;
            g_x0_lo[j] = __float2bfloat16_rn(v - __bfloat162float(hi));
        } else {
            long j = i - TU - TW - TX;
            float v = h0[j];
            __nv_bfloat16 hi = __float2bfloat16_rn(v);
            g_ahi[0][j] = hi;
            g_alo[0][j] = __float2bfloat16_rn(v - __bfloat162float(hi));
        }
    }
}

// ---------------- GEMM: C[64x64] += Asrc[64 x NC*64] * B(smem)^T, split-bf16 3-pass ----
template <int NC, int BPITCH>
__device__ __forceinline__ void run_gemm(
    const __nv_bfloat16 *__restrict__ gh, const __nv_bfloat16 *__restrict__ gl,
    int ldk, int m0, uint32_t smb, int tid, int lane, int wm, int wn, float C[4][4])
{
    // preload chunk 0 (A: 64 rows x 64 k, hi+lo, cp.async 16B units)
#pragma unroll
    for (int i = 0; i < 2; ++i) {
        int u = tid + 256 * i, m = u >> 3, kg = u & 7;
        size_t go = (size_t)(m0 + m) * ldk + kg * 8;
        uint32_t d = (uint32_t)(m * 128 + ((kg * 16) ^ ((m & 7) << 4)));
        cpa16(smb + d, gh + go);
        cpa16(smb + 8192 + d, gl + go);
    }
    CP_COMMIT;
    for (int kc = 0; kc < NC; ++kc) {
        CP_WAIT0;
        __syncthreads();
        uint32_t ab = smb + (kc & 1) * 16384;
        if (kc + 1 < NC) {
#pragma unroll
            for (int i = 0; i < 2; ++i) {
                int u = tid + 256 * i, m = u >> 3, kg = u & 7;
                size_t go = (size_t)(m0 + m) * ldk + (kc + 1) * 64 + kg * 8;
                uint32_t d = (uint32_t)(((kc + 1) & 1) * 16384 + m * 128 +
                                        ((kg * 16) ^ ((m & 7) << 4)));
                cpa16(smb + d, gh + go);
                cpa16(smb + 8192 + d, gl + go);
            }
            CP_COMMIT;
        }
#pragma unroll
        for (int sub = 0; sub < 4; ++sub) {
            uint32_t ahr[4], alr[4];
            {
                int mat = lane >> 3, rr = lane & 7;
                int mloc = wm * 16 + ((mat & 1) << 3) + rr;
                int kb = sub * 32 + ((mat >> 1) << 4);
                uint32_t off = mloc * 128 + (kb ^ ((mloc & 7) << 4));
                ldsm4(ab + off, ahr);
                ldsm4(ab + 8192 + off, alr);
            }
            uint32_t bhf[8], blf[8];
            const int kg2 = (kc * 64 + sub * 16) * 2;
#pragma unroll
            for (int half = 0; half < 2; ++half) {
                int mat = lane >> 3, rr = lane & 7;
                int nloc = wn * 32 + half * 16 + ((mat >> 1) << 3) + rr;
                int kb = kg2 + ((mat & 1) << 4);
                uint32_t off = nloc * BPITCH + (kb ^ ((nloc & 7) << 4));
                ldsm4(smb + SO_UH + off, &bhf[half * 4]);
                ldsm4(smb + SO_UL + off, &blf[half * 4]);
            }
#pragma unroll
            for (int nb = 0; nb < 4; ++nb) {
                mmabf(C[nb], ahr, bhf[nb * 2], bhf[nb * 2 + 1]);
                mmabf(C[nb], alr, bhf[nb * 2], bhf[nb * 2 + 1]);
                mmabf(C[nb], ahr, blf[nb * 2], blf[nb * 2 + 1]);
            }
        }
    }
    __syncthreads();
}

// ---------------- main persistent kernel ----------------
__global__ void __launch_bounds__(NTHR, 1) lstm_mma(
    const int *__restrict__ bsz, const float *__restrict__ h0in,
    const float *__restrict__ c0in, const float *__restrict__ taup,
    const float *__restrict__ Wb, float *__restrict__ out)
{
    extern __shared__ char sm[];
    const uint32_t smb = smem_u32(sm);
    const int tid = threadIdx.x, cta = blockIdx.x;
    const int lane = tid & 31, wid = tid >> 5;
    const int wm = wid & 3, wn = wid >> 2;
    const int mtile = cta & 3, ntile = cta >> 2;
    const int m0 = mtile * 64;
    const float tauv = __ldg(taup);

    const int cc = lane & 3;
    const int hbash = ntile * 16 + wn * 8 + (cc >> 1);
    const int mg0 = m0 + wm * 16 + (lane >> 2);

    // ---- fill W into U slots (pitch 512B), compute pre via MMA ----
    {
        char *p = sm;
#pragma unroll
        for (int i = 0; i < 8; ++i) {
            int u = tid + 256 * i, n = u >> 5, kg = u & 31;
            uint32_t d = n * 512 + ((kg * 16) ^ ((n & 7) << 4));
            *(uint4 *)(p + SO_UH + d) =
                *(const uint4 *)(g_Wt_hi + (size_t)(ntile * 64 + n) * 256 + kg * 8);
            *(uint4 *)(p + SO_UL + d) =
                *(const uint4 *)(g_Wt_lo + (size_t)(ntile * 64 + n) * 256 + kg * 8);
        }
    }
    __syncthreads();

    float C[4][4];
#pragma unroll
    for (int a = 0; a < 4; ++a)
#pragma unroll
        for (int r = 0; r < 4; ++r) C[a][r] = 0.0f;
    run_gemm<4, 512>(g_x0_hi, g_x0_lo, II, m0, smb, tid, lane, wm, wn, C);

    float pre[4][4];
#pragma unroll
    for (int nb = 0; nb < 4; ++nb)
#pragma unroll
        for (int r = 0; r < 4; ++r) {
            int gate = (cc * 2 + (r & 1)) & 3;
            int hg = ntile * 16 + wn * 8 + nb * 2 + (cc >> 1);
            pre[nb][r] = C[nb][r] + __ldg(Wb + gate * 512 + hg);
        }

    // ---- fill U resident (pitch 1024B) ----
    {
        char *p = sm;
#pragma unroll
        for (int i = 0; i < 16; ++i) {
            int u = tid + 256 * i, n = u >> 6, kg = u & 63;
            uint32_t d = n * 1024 + ((kg * 16) ^ ((n & 7) << 4));
            *(uint4 *)(p + SO_UH + d) =
                *(const uint4 *)(g_Ut_hi + (size_t)(ntile * 64 + n) * 512 + kg * 8);
            *(uint4 *)(p + SO_UL + d) =
                *(const uint4 *)(g_Ut_lo + (size_t)(ntile * 64 + n) * 512 + kg * 8);
        }
    }
    __syncthreads();

    // ---- per-thread cell states (4 cells: [p][mh]) ----
    float cs[2][2], hs[2][2];
#pragma unroll
    for (int p = 0; p < 2; ++p) {
        int nb = (lane & 1) ? 2 + p : p;
        int hg = hbash + nb * 2;
#pragma unroll
        for (int mh = 0; mh < 2; ++mh) {
            int mg = mg0 + mh * 8;
            cs[p][mh] = __ldg(c0in + (size_t)mg * 512 + hg);
            hs[p][mh] = __ldg(h0in + (size_t)mg * 512 + hg);
        }
    }

    // ---- time loop ----
    for (int t = 0; t < TT; ++t) {
#pragma unroll
        for (int a = 0; a < 4; ++a)
#pragma unroll
            for (int r = 0; r < 4; ++r) C[a][r] = 0.0f;
        run_gemm<8, 1024>(g_ahi[t & 1], g_alo[t & 1], HH, m0, smb, tid, lane, wm, wn, C);

        const int bs = __ldg(bsz + t);

        // gate sums = C + pre; exchange complementary gate pairs with lane^1
        float own[2][4], R[2][4];
#pragma unroll
        for (int p = 0; p < 2; ++p)
#pragma unroll
            for (int r = 0; r < 4; ++r) {
                float lo2 = C[p][r] + pre[p][r];
                float hi2 = C[2 + p][r] + pre[2 + p][r];
                own[p][r] = (lane & 1) ? hi2 : lo2;
                float send = (lane & 1) ? lo2 : hi2;
                R[p][r] = __shfl_xor_sync(0xffffffffu, send, 1);
            }

#pragma unroll
        for (int p = 0; p < 2; ++p) {
            int nb = (lane & 1) ? 2 + p : p;
            int hg = hbash + nb * 2;
#pragma unroll
            for (int mh = 0; mh < 2; ++mh) {
                float vi, vf, vg, vo;
                if (lane & 1) {
                    vg = own[p][mh * 2]; vo = own[p][mh * 2 + 1];
                    vi = R[p][mh * 2];   vf = R[p][mh * 2 + 1];
                } else {
                    vi = own[p][mh * 2]; vf = own[p][mh * 2 + 1];
                    vg = R[p][mh * 2];   vo = R[p][mh * 2 + 1];
                }
                int mg = mg0 + mh * 8;
                float cn = sigf(vf) * cs[p][mh] + sigf(vi) * tanhfast(vg);
                float hn = sigf(vo) * tanhfast(cn);
                bool act = (mg < bs);
                float o = act ? hn : 0.0f;
                if (act) { cs[p][mh] = cn; hs[p][mh] = hn; }
                out[(size_t)t * BH + (size_t)mg * 512 + hg] = o;
            }
        }

        if (t < TT - 1) {
            // drift on h dims 0,1 (owned by ntile 0, wn 0, nb 0 → lanes cc 0 and 2)
            if (ntile == 0 && wn == 0) {
#pragma unroll
                for (int mh = 0; mh < 2; ++mh) {
                    float mine = hs[0][mh];
                    float oth = __shfl_xor_sync(0xffffffffu, mine, 2);
                    if (!(lane & 1)) {
                        if (cc == 0)
                            hs[0][mh] = mine + tauv * (1.5f * mine + oth * (1.0f / 1.5f));
                        else if (cc == 2)
                            hs[0][mh] = mine - tauv * (1.5f * oth);
                    }
                }
            }
            __nv_bfloat16 *dh = g_ahi[(t + 1) & 1];
            __nv_bfloat16 *dl = g_alo[(t + 1) & 1];
#pragma unroll
            for (int p = 0; p < 2; ++p) {
                int nb = (lane & 1) ? 2 + p : p;
                int hg = hbash + nb * 2;
#pragma unroll
                for (int mh = 0; mh < 2; ++mh) {
                    int mg = mg0 + mh * 8;
                    float v = hs[p][mh];
                    __nv_bfloat16 bh16 = __float2bfloat16_rn(v);
                    dh[(size_t)mg * 512 + hg] = bh16;
                    dl[(size_t)mg * 512 + hg] =
                        __float2bfloat16_rn(v - __bfloat162float(bh16));
                }
            }
        }
        gridbar();
    }

    // ---- final h, c ----
    const size_t ofs = (size_t)TT * BH;
#pragma unroll
    for (int p = 0; p < 2; ++p) {
        int nb = (lane & 1) ? 2 + p : p;
        int hg = hbash + nb * 2;
#pragma unroll
        for (int mh = 0; mh < 2; ++mh) {
            int mg = mg0 + mh * 8;
            out[ofs + (size_t)mg * 512 + hg] = hs[p][mh];
            out[ofs + BH + (size_t)mg * 512 + hg] = cs[p][mh];
        }
    }
}

extern "C" void kernel_launch(void *const *d_in, const int *in_sizes, int n_in,
                              void *d_out, int out_size)
{
    const float *rnn = (const float *)d_in[0];
    const int *bsz = (const int *)d_in[1];
    const float *h0 = (const float *)d_in[2];
    const float *c0 = (const float *)d_in[3];
    const float *tau = (const float *)d_in[4];
    const float *Ww = (const float *)d_in[5];
    const float *Wb = (const float *)d_in[6];
    const float *Uw = (const float *)d_in[7];
    float *out = (float *)d_out;

    cudaFuncSetAttribute(lstm_mma, cudaFuncAttributeMaxDynamicSharedMemorySize,
                         SMEM_TOT);
    prep_kernel<<<512, 256>>>(rnn, h0, Ww, Uw);
    lstm_mma<<<NCTA, NTHR, SMEM_TOT>>>(bsz, h0, c0, tau, Wb, out);
}